// round 9
// baseline (speedup 1.0000x reference)
#include <cuda_runtime.h>
#include <cstdint>
#include <cstddef>

#define BB   4
#define NN   1024
#define DIMC 1024
#define HH   16
#define DHD  64

// Scratch (no cudaMalloc allowed)
__device__ float g_Q[(size_t)BB * NN * DIMC];
__device__ float g_K[(size_t)BB * NN * DIMC];
__device__ float g_V[(size_t)BB * NN * DIMC];
__device__ float g_O[(size_t)BB * NN * DIMC];
__device__ float g_Xr[(size_t)BB * NN * DIMC];
__device__ float g_Wqr[(size_t)DIMC * HH * DHD];
__device__ float g_Wkr[(size_t)DIMC * HH * DHD];
__device__ float g_Wvr[(size_t)DIMC * HH * DHD];
__device__ float g_Wor[(size_t)HH * DHD * DIMC];
__device__ float g_inv[(size_t)BB * HH * NN];        // 1/rowsum

__device__ __forceinline__ float tf32r(float x) {
    uint32_t u;
    asm("cvt.rna.tf32.f32 %0, %1;" : "=r"(u) : "f"(x));
    return __uint_as_float(u);
}

__device__ __forceinline__ void cp16(float* smem, const float* gmem) {
    uint32_t s = (uint32_t)__cvta_generic_to_shared(smem);
    asm volatile("cp.async.cg.shared.global [%0], [%1], 16;" :: "r"(s), "l"(gmem));
}
__device__ __forceinline__ void cp_commit() { asm volatile("cp.async.commit_group;"); }
__device__ __forceinline__ void cp_wait1()  { asm volatile("cp.async.wait_group 1;"); }
__device__ __forceinline__ void cp_wait2()  { asm volatile("cp.async.wait_group 2;"); }

#define MMA_TF32(d, a0, a1, a2, a3, b0, b1)                                 \
    asm volatile(                                                           \
        "mma.sync.aligned.m16n8k8.row.col.f32.tf32.tf32.f32 "               \
        "{%0,%1,%2,%3}, {%4,%5,%6,%7}, {%8,%9}, {%0,%1,%2,%3};"             \
        : "+f"(d[0]), "+f"(d[1]), "+f"(d[2]), "+f"(d[3])                    \
        : "r"(a0), "r"(a1), "r"(a2), "r"(a3), "r"(b0), "r"(b1))

// ---------------------------------------------------------------------------
// Pre-round x and all weights to tf32 (rna) once.
// ---------------------------------------------------------------------------
__global__ __launch_bounds__(256) void round_all(
    const float* __restrict__ x,
    const float* __restrict__ Wq, const float* __restrict__ Wk,
    const float* __restrict__ Wv, const float* __restrict__ Wo,
    float* __restrict__ xr,
    float* __restrict__ wqr, float* __restrict__ wkr,
    float* __restrict__ wvr, float* __restrict__ wor)
{
    int i = blockIdx.x * blockDim.x + threadIdx.x;   // float4 index, 2M total
    const float* src; float* dst; int off;
    if (i < (1 << 20)) { src = x; dst = xr; off = i; }
    else {
        int j = i - (1 << 20);
        int w = j >> 18; off = j & ((1 << 18) - 1);
        src = (w == 0) ? Wq : (w == 1) ? Wk : (w == 2) ? Wv : Wo;
        dst = (w == 0) ? wqr : (w == 1) ? wkr : (w == 2) ? wvr : wor;
    }
    float4 v = ((const float4*)src)[off];
    v.x = tf32r(v.x); v.y = tf32r(v.y); v.z = tf32r(v.z); v.w = tf32r(v.w);
    ((float4*)dst)[off] = v;
}

// ---------------------------------------------------------------------------
// tf32 GEMM, 512 threads, 128x128 tile, BK=16, 3-stage cp.async pipeline.
// ---------------------------------------------------------------------------
#define GEMM_SMEM ((3 * 128 * 20 + 3 * 16 * 136) * 4)   // 56832 B

template<bool ROUND_OUT>
__device__ __forceinline__ void gemm_body(
    const float* __restrict__ A, const float* __restrict__ Bm,
    float* __restrict__ C, const float* __restrict__ bias,
    float outScale, int K, int Nc)
{
    extern __shared__ float smg[];
    float* As = smg;                    // [3][128][20]
    float* Bs = smg + 3 * 2560;         // [3][16][136]

    const int t     = threadIdx.x;
    const int wid   = t >> 5, lane = t & 31;
    const int group = lane >> 2, tig = lane & 3;
    const int wm    = (wid & 3) * 32;
    const int wn    = (wid >> 2) * 32;
    const int m0    = blockIdx.y * 128;
    const int n0    = blockIdx.x * 128;

    auto load_stage = [&](int s, int k0) {
        float* Ad = As + s * 2560;
        float* Bd = Bs + s * 2176;
        {
            int r = t >> 2, k4 = (t & 3) * 4;
            cp16(Ad + r * 20 + k4, A + (size_t)(m0 + r) * K + k0 + k4);
        }
        {
            int kr = t >> 5, b4 = (t & 31) * 4;
            cp16(Bd + kr * 136 + (b4 ^ ((kr & 12) << 1)),
                 Bm + (size_t)(k0 + kr) * Nc + n0 + b4);
        }
    };

    float acc[2][4][4] = {};

    load_stage(0, 0);  cp_commit();
    load_stage(1, 16); cp_commit();

    int s = 0;
    for (int k0 = 0; k0 < K; k0 += 16) {
        cp_wait1();
        __syncthreads();
        int s2 = (s >= 1) ? s - 1 : s + 2;
        if (k0 + 32 < K) load_stage(s2, k0 + 32);
        cp_commit();

        const float* Ac = As + s * 2560;
        const float* Bc = Bs + s * 2176;
        #pragma unroll
        for (int ks = 0; ks < 2; ks++) {
            int kk = ks * 8;
            int s0 = kk << 1;
            int s1 = ((kk + 4) & 12) << 1;
            uint32_t a[2][4];
            #pragma unroll
            for (int mf = 0; mf < 2; mf++) {
                int mb = wm + mf * 16;
                a[mf][0] = __float_as_uint(Ac[(mb + group    ) * 20 + kk + tig    ]);
                a[mf][1] = __float_as_uint(Ac[(mb + group + 8) * 20 + kk + tig    ]);
                a[mf][2] = __float_as_uint(Ac[(mb + group    ) * 20 + kk + tig + 4]);
                a[mf][3] = __float_as_uint(Ac[(mb + group + 8) * 20 + kk + tig + 4]);
            }
            #pragma unroll
            for (int nf = 0; nf < 4; nf++) {
                int nb = wn + nf * 8;
                uint32_t b0 = __float_as_uint(Bc[(kk + tig    ) * 136 + ((nb + group) ^ s0)]);
                uint32_t b1 = __float_as_uint(Bc[(kk + tig + 4) * 136 + ((nb + group) ^ s1)]);
                #pragma unroll
                for (int mf = 0; mf < 2; mf++)
                    MMA_TF32(acc[mf][nf], a[mf][0], a[mf][1], a[mf][2], a[mf][3], b0, b1);
            }
        }
        s = (s == 2) ? 0 : s + 1;
        __syncthreads();
    }

    #pragma unroll
    for (int mf = 0; mf < 2; mf++) {
        #pragma unroll
        for (int nf = 0; nf < 4; nf++) {
            int row = m0 + wm + mf * 16 + group;
            int col = n0 + wn + nf * 8 + tig * 2;
            float v0, v1, v2, v3;
            if (ROUND_OUT) {
                v0 = tf32r(acc[mf][nf][0] * outScale);
                v1 = tf32r(acc[mf][nf][1] * outScale);
                v2 = tf32r(acc[mf][nf][2] * outScale);
                v3 = tf32r(acc[mf][nf][3] * outScale);
            } else {
                float bx = bias[col], by = bias[col + 1];
                v0 = acc[mf][nf][0] + bx; v1 = acc[mf][nf][1] + by;
                v2 = acc[mf][nf][2] + bx; v3 = acc[mf][nf][3] + by;
            }
            *(float2*)(C + (size_t)row       * Nc + col) = make_float2(v0, v1);
            *(float2*)(C + (size_t)(row + 8) * Nc + col) = make_float2(v2, v3);
        }
    }
}

__global__ __launch_bounds__(512) void gemm_qkv(
    const float* __restrict__ x,
    const float* __restrict__ Wq, const float* __restrict__ Wk,
    const float* __restrict__ Wv,
    float* __restrict__ Qo, float* __restrict__ Ko, float* __restrict__ Vo)
{
    const float* W = (blockIdx.z == 0) ? Wq : (blockIdx.z == 1) ? Wk : Wv;
    float*       C = (blockIdx.z == 0) ? Qo : (blockIdx.z == 1) ? Ko : Vo;
    float scale    = (blockIdx.z == 0) ? 0.125f : 1.0f;
    gemm_body<true>(x, W, C, nullptr, scale, DIMC, HH * DHD);
}

__global__ __launch_bounds__(512) void gemm_out(
    const float* __restrict__ A, const float* __restrict__ W,
    float* __restrict__ C, const float* __restrict__ bias)
{
    gemm_body<false>(A, W, C, bias, 1.0f, DIMC, DIMC);
}

// ---------------------------------------------------------------------------
// qk_sums: per (m-tile, head): loop over all 8 K-chunks with double-buffered
// cp.async. Q tile held as register fragments. Writes E = exp(S) and the
// per-row inverse sums (1/rowsum) directly. No max subtraction (scores O(10)).
// ---------------------------------------------------------------------------
#define QKS_SMEM ((128 * 68 + 2 * 128 * 68) * 4)   // 104448 B

__global__ __launch_bounds__(512) void qk_sums(
    const float* __restrict__ Q, const float* __restrict__ Kt,
    float* __restrict__ Sexp, float* __restrict__ inv)
{
    extern __shared__ float smq[];
    float* Qs = smq;                 // [128][68]
    float* Ks = smq + 128 * 68;      // [2][128][68]
    __shared__ float rowpart[128][4];

    const int t     = threadIdx.x;
    const int wid   = t >> 5, lane = t & 31;
    const int group = lane >> 2, tig = lane & 3;
    const int wm    = (wid & 3) * 32;
    const int wn    = (wid >> 2) * 32;
    const int m0    = blockIdx.x * 128;
    const int bh    = blockIdx.y;
    const int b     = bh >> 4, h = bh & 15;
    const size_t base = (size_t)b * NN * DIMC + (size_t)h * DHD;

    auto loadK = [&](int buf, int c) {
        float* Td = Ks + buf * (128 * 68);
        #pragma unroll
        for (int p = 0; p < 4; p++) {
            int l = p * 512 + t;
            int r = l >> 4, d4 = (l & 15) * 4;
            cp16(Td + r * 68 + d4, Kt + base + (size_t)(c * 128 + r) * DIMC + d4);
        }
    };

    // G0: Q tile
    #pragma unroll
    for (int p = 0; p < 4; p++) {
        int l = p * 512 + t;
        int r = l >> 4, d4 = (l & 15) * 4;
        cp16(Qs + r * 68 + d4, Q + base + (size_t)(m0 + r) * DIMC + d4);
    }
    cp_commit();
    loadK(0, 0); cp_commit();    // G1
    loadK(1, 1); cp_commit();    // G2

    cp_wait2();                  // Q resident
    __syncthreads();

    // Q fragments -> registers (reused for all 8 chunks)
    uint32_t qa[2][8][4];
    #pragma unroll
    for (int ks = 0; ks < 8; ks++) {
        int kk = ks * 8;
        #pragma unroll
        for (int mf = 0; mf < 2; mf++) {
            int mb = wm + mf * 16;
            qa[mf][ks][0] = __float_as_uint(Qs[(mb + group    ) * 68 + kk + tig    ]);
            qa[mf][ks][1] = __float_as_uint(Qs[(mb + group + 8) * 68 + kk + tig    ]);
            qa[mf][ks][2] = __float_as_uint(Qs[(mb + group    ) * 68 + kk + tig + 4]);
            qa[mf][ks][3] = __float_as_uint(Qs[(mb + group + 8) * 68 + kk + tig + 4]);
        }
    }

    float sr[4] = {0.f, 0.f, 0.f, 0.f};   // row-sum accumulators [mf][a/b]

    for (int c = 0; c < 8; c++) {
        cp_wait1();              // K chunk c resident
        __syncthreads();

        const float* Tc = Ks + (c & 1) * (128 * 68);
        float acc[2][4][4] = {};
        #pragma unroll
        for (int ks = 0; ks < 8; ks++) {
            int kk = ks * 8;
            #pragma unroll
            for (int nf = 0; nf < 4; nf++) {
                int nb = wn + nf * 8;
                uint32_t b0 = __float_as_uint(Tc[(nb + group) * 68 + kk + tig    ]);
                uint32_t b1 = __float_as_uint(Tc[(nb + group) * 68 + kk + tig + 4]);
                #pragma unroll
                for (int mf = 0; mf < 2; mf++)
                    MMA_TF32(acc[mf][nf], qa[mf][ks][0], qa[mf][ks][1],
                             qa[mf][ks][2], qa[mf][ks][3], b0, b1);
            }
        }

        // exp + store + accumulate row sums
        float* Sb = Sexp + ((size_t)bh * NN + m0) * NN + c * 128;
        #pragma unroll
        for (int mf = 0; mf < 2; mf++) {
            #pragma unroll
            for (int nf = 0; nf < 4; nf++) {
                float e0 = __expf(acc[mf][nf][0]);
                float e1 = __expf(acc[mf][nf][1]);
                float e2 = __expf(acc[mf][nf][2]);
                float e3 = __expf(acc[mf][nf][3]);
                sr[mf * 2    ] += e0 + e1;
                sr[mf * 2 + 1] += e2 + e3;
                int row = wm + mf * 16 + group;
                int col = wn + nf * 8 + tig * 2;
                *(float2*)(Sb + (size_t)row       * NN + col) = make_float2(e0, e1);
                *(float2*)(Sb + (size_t)(row + 8) * NN + col) = make_float2(e2, e3);
            }
        }

        __syncthreads();         // everyone done with buffer (c&1)
        if (c < 6) loadK(c & 1, c + 2);
        cp_commit();
    }

    // reduce sums: over tig lanes, then over the 4 n-warp groups
    #pragma unroll
    for (int i = 0; i < 4; i++) {
        sr[i] += __shfl_xor_sync(0xffffffffu, sr[i], 1);
        sr[i] += __shfl_xor_sync(0xffffffffu, sr[i], 2);
    }
    if (tig == 0) {
        #pragma unroll
        for (int mf = 0; mf < 2; mf++) {
            rowpart[wm + mf * 16 + group    ][wid >> 2] = sr[mf * 2    ];
            rowpart[wm + mf * 16 + group + 8][wid >> 2] = sr[mf * 2 + 1];
        }
    }
    __syncthreads();
    if (t < 128) {
        float ssum = rowpart[t][0] + rowpart[t][1] + rowpart[t][2] + rowpart[t][3];
        inv[(size_t)bh * NN + m0 + t] = 1.f / ssum;
    }
}

// ---------------------------------------------------------------------------
// pv_fused: O = (E * inv) @ V ; also writes normalized attn in-place from
// staged smem. 256x64 tile, 512 threads, 16 warps (8m x 2n), 3-stage cp.async.
// ---------------------------------------------------------------------------
#define PV_SMEM ((3 * 256 * 20 + 3 * 16 * 72) * 4)   // 75264 B

__global__ __launch_bounds__(512) void pv_fused(
    float* __restrict__ P, const float* __restrict__ V,
    const float* __restrict__ inv, float* __restrict__ O)
{
    extern __shared__ float smp[];
    float* As = smp;                    // [3][256][20]
    float* Bs = smp + 3 * 5120;         // [3][16][72]

    const int t     = threadIdx.x;
    const int wid   = t >> 5, lane = t & 31;
    const int group = lane >> 2, tig = lane & 3;
    const int wm    = (wid & 7) * 32;
    const int wn    = (wid >> 3) * 32;
    const int m0    = blockIdx.x * 256;
    const int h     = blockIdx.y, b = blockIdx.z;

    const size_t rowbase = ((size_t)b * HH + h) * NN + m0;
    float*       Pb = P + rowbase * NN;
    const float* Vb = V + (size_t)b * NN * DIMC + (size_t)h * DHD;
    float*       Ob = O + (size_t)b * NN * DIMC + (size_t)h * DHD;

    float fi[4];
    #pragma unroll
    for (int mf = 0; mf < 2; mf++) {
        fi[mf * 2    ] = inv[rowbase + wm + mf * 16 + group    ];
        fi[mf * 2 + 1] = inv[rowbase + wm + mf * 16 + group + 8];
    }
    float wi[2];
    #pragma unroll
    for (int l = 0; l < 2; l++) wi[l] = inv[rowbase + ((l * 512 + t) >> 2)];

    auto load_stage = [&](int s, int k0) {
        float* Ad = As + s * 5120;
        float* Bd = Bs + s * 1152;
        #pragma unroll
        for (int l = 0; l < 2; l++) {
            int c = l * 512 + t;
            int r = c >> 2, k4 = (c & 3) * 4;
            cp16(Ad + r * 20 + k4, Pb + (size_t)r * NN + k0 + k4);
        }
        if (t < 256) {
            int kr = t >> 4, n4 = (t & 15) * 4;
            cp16(Bd + kr * 72 + n4, Vb + (size_t)(k0 + kr) * DIMC + n4);
        }
    };

    float acc[2][4][4] = {};

    load_stage(0, 0);  cp_commit();
    load_stage(1, 16); cp_commit();

    int s = 0;
    for (int k0 = 0; k0 < NN; k0 += 16) {
        cp_wait1();
        __syncthreads();
        int s2 = (s >= 1) ? s - 1 : s + 2;
        if (k0 + 32 < NN) load_stage(s2, k0 + 32);
        cp_commit();

        const float* Ac = As + s * 5120;
        const float* Bc = Bs + s * 1152;

        // write normalized attn chunk back to gmem (from staged raw expS)
        #pragma unroll
        for (int l = 0; l < 2; l++) {
            int c = l * 512 + t;
            int r = c >> 2, k4 = (c & 3) * 4;
            const float* src = Ac + r * 20 + k4;
            float4 v;
            v.x = src[0] * wi[l]; v.y = src[1] * wi[l];
            v.z = src[2] * wi[l]; v.w = src[3] * wi[l];
            *(float4*)(Pb + (size_t)r * NN + k0 + k4) = v;
        }

        #pragma unroll
        for (int ks = 0; ks < 2; ks++) {
            int kk = ks * 8;
            uint32_t a[2][4];
            #pragma unroll
            for (int mf = 0; mf < 2; mf++) {
                int mb = wm + mf * 16;
                a[mf][0] = __float_as_uint(tf32r(Ac[(mb + group    ) * 20 + kk + tig    ] * fi[mf * 2    ]));
                a[mf][1] = __float_as_uint(tf32r(Ac[(mb + group + 8) * 20 + kk + tig    ] * fi[mf * 2 + 1]));
                a[mf][2] = __float_as_uint(tf32r(Ac[(mb + group    ) * 20 + kk + tig + 4] * fi[mf * 2    ]));
                a[mf][3] = __float_as_uint(tf32r(Ac[(mb + group + 8) * 20 + kk + tig + 4] * fi[mf * 2 + 1]));
            }
            #pragma unroll
            for (int nf = 0; nf < 4; nf++) {
                int nb = wn + nf * 8;
                uint32_t b0 = __float_as_uint(Bc[(kk + tig    ) * 72 + nb + group]);
                uint32_t b1 = __float_as_uint(Bc[(kk + tig + 4) * 72 + nb + group]);
                #pragma unroll
                for (int mf = 0; mf < 2; mf++)
                    MMA_TF32(acc[mf][nf], a[mf][0], a[mf][1], a[mf][2], a[mf][3], b0, b1);
            }
        }
        s = (s == 2) ? 0 : s + 1;
        __syncthreads();
    }

    #pragma unroll
    for (int mf = 0; mf < 2; mf++) {
        #pragma unroll
        for (int nf = 0; nf < 4; nf++) {
            int row = m0 + wm + mf * 16 + group;
            int col = wn + nf * 8 + tig * 2;
            *(float2*)(Ob + (size_t)row       * DIMC + col) =
                make_float2(tf32r(acc[mf][nf][0]), tf32r(acc[mf][nf][1]));
            *(float2*)(Ob + (size_t)(row + 8) * DIMC + col) =
                make_float2(tf32r(acc[mf][nf][2]), tf32r(acc[mf][nf][3]));
        }
    }
}

// ---------------------------------------------------------------------------
extern "C" void kernel_launch(void* const* d_in, const int* in_sizes, int n_in,
                              void* d_out, int out_size)
{
    const float* x  = (const float*)d_in[0];
    const float* Wq = (const float*)d_in[1];
    const float* Wk = (const float*)d_in[2];
    const float* Wv = (const float*)d_in[3];
    const float* Wo = (const float*)d_in[4];
    const float* bo = (const float*)d_in[5];

    float* out  = (float*)d_out;
    float* attn = out + (size_t)BB * NN * DIMC;

    float *Qp, *Kp, *Vp, *Op, *Xr, *Wqr, *Wkr, *Wvr, *Wor, *Iv;
    cudaGetSymbolAddress((void**)&Qp,  g_Q);
    cudaGetSymbolAddress((void**)&Kp,  g_K);
    cudaGetSymbolAddress((void**)&Vp,  g_V);
    cudaGetSymbolAddress((void**)&Op,  g_O);
    cudaGetSymbolAddress((void**)&Xr,  g_Xr);
    cudaGetSymbolAddress((void**)&Wqr, g_Wqr);
    cudaGetSymbolAddress((void**)&Wkr, g_Wkr);
    cudaGetSymbolAddress((void**)&Wvr, g_Wvr);
    cudaGetSymbolAddress((void**)&Wor, g_Wor);
    cudaGetSymbolAddress((void**)&Iv,  g_inv);

    cudaFuncSetAttribute(gemm_qkv, cudaFuncAttributeMaxDynamicSharedMemorySize, GEMM_SMEM);
    cudaFuncSetAttribute(gemm_out, cudaFuncAttributeMaxDynamicSharedMemorySize, GEMM_SMEM);
    cudaFuncSetAttribute(qk_sums,  cudaFuncAttributeMaxDynamicSharedMemorySize, QKS_SMEM);
    cudaFuncSetAttribute(pv_fused, cudaFuncAttributeMaxDynamicSharedMemorySize, PV_SMEM);

    round_all<<<8192, 256>>>(x, Wq, Wk, Wv, Wo, Xr, Wqr, Wkr, Wvr, Wor);

    dim3 gQKV(8, 32, 3);
    gemm_qkv<<<gQKV, 512, GEMM_SMEM>>>(Xr, Wqr, Wkr, Wvr, Qp, Kp, Vp);

    dim3 gQK(8, BB * HH);    // (m-tiles, b*16+h)
    qk_sums<<<gQK, 512, QKS_SMEM>>>(Qp, Kp, attn, Iv);

    dim3 gPV(NN / 256, HH, BB);
    pv_fused<<<gPV, 512, PV_SMEM>>>(attn, Vp, Iv, Op);

    dim3 gOut(8, 32);
    gemm_out<<<gOut, 512, GEMM_SMEM>>>(Op, Wor, out, bo);
}